// round 11
// baseline (speedup 1.0000x reference)
#include <cuda_runtime.h>
#include <cstdint>

#define W   256
#define NB  128     // n = hn*bs
#define C   128
#define NE  8       // heads
#define HD  16
#define D2  511     // 2W-1
#define ROWS (W*NB) // 32768
#define HN  64

// ---------------- scratch (device globals; no allocation) ----------------
__device__ float g_fl[ROWS*C];
__device__ float g_fr[ROWS*C];
__device__ float g_fl2[ROWS*C];
__device__ float g_fr2[ROWS*C];
__device__ float g_q[ROWS*C];          // reused as vo (q dead after k_scores/k_rawsum)
__device__ float g_kv[ROWS*2*C];
__device__ float g_qr[D2*C];
__device__ float g_kr[D2*C];
__device__ float g_attn[(size_t)NB*NE*W*W];   // raw scores, 268 MB

// ---------------- reorder in (z-batched over both inputs): (bs,c,hn,w) -> X[i][j][cc] ----
// gridDim.z = 256: hb = z & 127 (h = hb>>1 in [0,64), b = hb&1), s = z >> 7 selects tensor
__global__ void k_reorder_in(const float* __restrict__ inA, float* __restrict__ outA,
                             const float* __restrict__ inB, float* __restrict__ outB) {
    __shared__ float sm[32][33];
    int itile = blockIdx.x*32, cctile = blockIdx.y*32;
    int hb = blockIdx.z & 127, s = blockIdx.z >> 7;
    const float* in = s ? inB : inA;
    float* out = s ? outB : outA;
    int h = hb >> 1, b = hb & 1, j = h*2 + b;
    int tx = threadIdx.x, ty = threadIdx.y;
    #pragma unroll
    for (int r = 0; r < 32; r += 8) {
        int cc = cctile + r + ty;
        sm[r+ty][tx] = in[ ((b*C + cc)*HN + h)*W + itile + tx ];
    }
    __syncthreads();
    #pragma unroll
    for (int r = 0; r < 32; r += 8) {
        int i = itile + r + ty;
        out[ (i*NB + j)*C + cctile + tx ] = sm[tx][r+ty];
    }
}

// ---------------- reorder out (z-batched, same z mapping) ----------------
__global__ void k_reorder_out(const float* __restrict__ XA, float* __restrict__ outA,
                              const float* __restrict__ XB, float* __restrict__ outB) {
    __shared__ float sm[32][33];
    int itile = blockIdx.x*32, cctile = blockIdx.y*32;
    int hb = blockIdx.z & 127, s = blockIdx.z >> 7;
    const float* X = s ? XB : XA;
    float* out = s ? outB : outA;
    int h = hb >> 1, b = hb & 1, j = h*2 + b;
    int tx = threadIdx.x, ty = threadIdx.y;
    #pragma unroll
    for (int r = 0; r < 32; r += 8) {
        int i = itile + r + ty;
        sm[r+ty][tx] = X[ (i*NB + j)*C + cctile + tx ];
    }
    __syncthreads();
    #pragma unroll
    for (int r = 0; r < 32; r += 8) {
        int cc = cctile + r + ty;
        out[ ((b*C + cc)*HN + h)*W + itile + tx ] = sm[tx][r+ty];
    }
}

// ---------------- layernorm (optionally y-batched over two tensors) ----------------
__global__ void k_layernorm2(const float* __restrict__ XA, float* __restrict__ YA,
                             const float* __restrict__ XB, float* __restrict__ YB,
                             const float* __restrict__ g, const float* __restrict__ b) {
    int row = blockIdx.x;
    const float* X = blockIdx.y ? XB : XA;
    float* Y = blockIdx.y ? YB : YA;
    int t = threadIdx.x;
    float x = X[row*C + t];
    __shared__ float red[4];
    float s = x;
    #pragma unroll
    for (int o = 16; o; o >>= 1) s += __shfl_xor_sync(0xffffffffu, s, o);
    if ((t & 31) == 0) red[t >> 5] = s;
    __syncthreads();
    float mean = (red[0]+red[1]+red[2]+red[3]) * (1.0f/C);
    float d = x - mean;
    float s2 = d*d;
    #pragma unroll
    for (int o = 16; o; o >>= 1) s2 += __shfl_xor_sync(0xffffffffu, s2, o);
    __syncthreads();
    if ((t & 31) == 0) red[t >> 5] = s2;
    __syncthreads();
    float var = (red[0]+red[1]+red[2]+red[3]) * (1.0f/C);
    Y[row*C + t] = d * rsqrtf(var + 1e-5f) * g[t] + b[t];
}

// ---------------- GEMM tile body (64 rows x 128 cols, K=128 chunked by 32) ----------------
__device__ __forceinline__ void gemm_tile(const float* __restrict__ A, const float* __restrict__ Wr,
                                          const float* __restrict__ bias, const float* __restrict__ res,
                                          float* __restrict__ Cout, int M, float scale, int ldc,
                                          float* As, float* Bs) {
    int m0 = blockIdx.x*64;
    if (m0 >= M) return;
    int tid = threadIdx.x;
    int tx = tid & 15, ty = tid >> 4;
    float acc[4][8] = {};

    for (int kc = 0; kc < 128; kc += 32) {
        __syncthreads();
        #pragma unroll
        for (int rep = 0; rep < 2; rep++) {
            int f4 = tid + rep*256;
            int m = f4 >> 3, k4 = f4 & 7;
            int gm = m0 + m;
            float4 v = (gm < M) ? *(const float4*)&A[(size_t)gm*128 + kc + k4*4]
                                : make_float4(0.f,0.f,0.f,0.f);
            As[(4*k4+0)*68 + m] = v.x;
            As[(4*k4+1)*68 + m] = v.y;
            As[(4*k4+2)*68 + m] = v.z;
            As[(4*k4+3)*68 + m] = v.w;
        }
        #pragma unroll
        for (int rep = 0; rep < 4; rep++) {
            int f4 = tid + rep*256;
            int n = f4 >> 3, k4 = f4 & 7;
            float4 v = *(const float4*)&Wr[(size_t)n*128 + kc + k4*4];
            Bs[(4*k4+0)*132 + n] = v.x;
            Bs[(4*k4+1)*132 + n] = v.y;
            Bs[(4*k4+2)*132 + n] = v.z;
            Bs[(4*k4+3)*132 + n] = v.w;
        }
        __syncthreads();
        #pragma unroll
        for (int kk = 0; kk < 32; kk++) {
            float4 a  = *(float4*)&As[kk*68 + 4*ty];
            float4 b0 = *(float4*)&Bs[kk*132 + 4*tx];
            float4 b1 = *(float4*)&Bs[kk*132 + 64 + 4*tx];
            float av[4] = {a.x, a.y, a.z, a.w};
            float bv[8] = {b0.x, b0.y, b0.z, b0.w, b1.x, b1.y, b1.z, b1.w};
            #pragma unroll
            for (int r = 0; r < 4; r++)
                #pragma unroll
                for (int c = 0; c < 8; c++) acc[r][c] += av[r]*bv[c];
        }
    }

    float4 bi0 = *(const float4*)&bias[4*tx];
    float4 bi1 = *(const float4*)&bias[64 + 4*tx];
    float bb[8] = {bi0.x, bi0.y, bi0.z, bi0.w, bi1.x, bi1.y, bi1.z, bi1.w};
    #pragma unroll
    for (int r = 0; r < 4; r++) {
        int gm = m0 + 4*ty + r;
        if (gm >= M) continue;
        float o[8];
        #pragma unroll
        for (int c = 0; c < 8; c++) o[c] = scale * (acc[r][c] + bb[c]);
        size_t base = (size_t)gm*ldc;
        if (res) {
            float4 r0 = *(const float4*)&res[base + 4*tx];
            float4 r1 = *(const float4*)&res[base + 64 + 4*tx];
            o[0]+=r0.x; o[1]+=r0.y; o[2]+=r0.z; o[3]+=r0.w;
            o[4]+=r1.x; o[5]+=r1.y; o[6]+=r1.z; o[7]+=r1.w;
        }
        *(float4*)&Cout[base + 4*tx]      = make_float4(o[0],o[1],o[2],o[3]);
        *(float4*)&Cout[base + 64 + 4*tx] = make_float4(o[4],o[5],o[6],o[7]);
    }
}

__global__ __launch_bounds__(256, 4)
void k_gemm(const float* __restrict__ A, const float* __restrict__ Wr,
            const float* __restrict__ bias, const float* __restrict__ res,
            float* __restrict__ Cout, int M, float scale, int ldc) {
    __shared__ __align__(16) float As[32*68];
    __shared__ __align__(16) float Bs[32*132];
    gemm_tile(A, Wr, bias, res, Cout, M, scale, ldc, As, Bs);
}

// batched projections: z=0 q, z=1 K, z=2 V, z=3 qr, z=4 kr
__global__ __launch_bounds__(256, 4)
void k_gemm_qkv(const float* __restrict__ Aq, const float* __restrict__ Akv,
                const float* __restrict__ pos,
                const float* __restrict__ Wqkv, const float* __restrict__ bqkv,
                float* __restrict__ q, float* __restrict__ kv,
                float* __restrict__ qr, float* __restrict__ kr) {
    __shared__ __align__(16) float As[32*68];
    __shared__ __align__(16) float Bs[32*132];
    int z = blockIdx.z;
    switch (z) {
        case 0: gemm_tile(Aq,  Wqkv,           bqkv,     nullptr, q,      ROWS, 0.25f, 128, As, Bs); break;
        case 1: gemm_tile(Akv, Wqkv + 128*128, bqkv+128, nullptr, kv,     ROWS, 1.0f,  256, As, Bs); break;
        case 2: gemm_tile(Akv, Wqkv + 256*128, bqkv+256, nullptr, kv+128, ROWS, 1.0f,  256, As, Bs); break;
        case 3: gemm_tile(pos, Wqkv,           bqkv,     nullptr, qr,     D2,   0.25f, 128, As, Bs); break;
        case 4: gemm_tile(pos, Wqkv + 128*128, bqkv+128, nullptr, kr,     D2,   1.0f,  128, As, Bs); break;
    }
}

// ---------------- scores: attn[n,e,i,v] = q·k + q·kr[d] + qr[d]·k, d = 255+sgn*(i-v) ----
__global__ __launch_bounds__(256, 3)
void k_scores(const float* __restrict__ q, const float* __restrict__ kv,
              const float* __restrict__ qr, const float* __restrict__ kr,
              float* __restrict__ attn, int sgn) {
    __shared__ float Qs[64*17];
    __shared__ float Ks[128*17];
    __shared__ float QRs[192*17];
    __shared__ float KRs[192*17];
    int i0 = (blockIdx.x >> 1) * 64;
    int v0 = (blockIdx.x & 1) * 128;
    int e = blockIdx.y, n = blockIdx.z;
    int tid = threadIdx.x;
    int dmin = (sgn > 0) ? (128 + i0 - v0) : (192 - i0 + v0);
    for (int idx = tid; idx < 64*16; idx += 256) {
        int r = idx >> 4, cc = idx & 15;
        Qs[r*17+cc] = q[(size_t)((i0+r)*NB + n)*C + e*16 + cc];
    }
    for (int idx = tid; idx < 128*16; idx += 256) {
        int r = idx >> 4, cc = idx & 15;
        Ks[r*17+cc] = kv[(size_t)((v0+r)*NB + n)*(2*C) + e*16 + cc];
    }
    for (int idx = tid; idx < 192*16; idx += 256) {
        int r = idx >> 4, cc = idx & 15;
        QRs[r*17+cc] = qr[(dmin+r)*C + e*16 + cc];
        KRs[r*17+cc] = kr[(dmin+r)*C + e*16 + cc];
    }
    __syncthreads();
    int ty = tid & 15, tx = tid >> 4;
    int ib = ty*4, vb = tx*8;
    int dbase = (sgn > 0) ? (127 + ib - vb) : (63 - ib + vb);
    int doff[11];
    #pragma unroll
    for (int k = 0; k < 11; k++) doff[k] = (dbase + sgn*(k - 7))*17;
    float acc[4][8] = {};
    #pragma unroll 2
    for (int cc = 0; cc < 16; cc++) {
        float qa[4], ka[8], qrl[11], krl[11];
        #pragma unroll
        for (int r = 0; r < 4; r++) qa[r] = Qs[(ib+r)*17 + cc];
        #pragma unroll
        for (int r = 0; r < 8; r++) ka[r] = Ks[(vb+r)*17 + cc];
        #pragma unroll
        for (int k = 0; k < 11; k++) { qrl[k] = QRs[doff[k] + cc]; krl[k] = KRs[doff[k] + cc]; }
        #pragma unroll
        for (int ri = 0; ri < 4; ri++)
            #pragma unroll
            for (int rv = 0; rv < 8; rv++) {
                int k = ri - rv + 7;
                acc[ri][rv] += qa[ri]*(ka[rv] + krl[k]) + qrl[k]*ka[rv];
            }
    }
    #pragma unroll
    for (int ri = 0; ri < 4; ri++) {
        int i = i0 + ib + ri;
        float4* dst = (float4*)&attn[ ((size_t)(n*NE + e)*W + i)*W + v0 + vb ];
        dst[0] = make_float4(acc[ri][0], acc[ri][1], acc[ri][2], acc[ri][3]);
        dst[1] = make_float4(acc[ri][4], acc[ri][5], acc[ri][6], acc[ri][7]);
    }
}

// ---------------- rawsum: rawout[(b,h),i,v] = sum_e attn[n,e,i,v] (memory-bound) --------
__global__ void k_rawsum(const float* __restrict__ attn, float* __restrict__ rawout) {
    int i = blockIdx.x, n = blockIdx.y;
    int v = threadIdx.x;   // 256
    const float* base = attn + ((size_t)(n*NE)*W + i)*W + v;
    float s = 0.f;
    #pragma unroll
    for (int e = 0; e < NE; e++) s += base[(size_t)e*W*W];
    int b = n & 1, h = n >> 1;
    rawout[ ((size_t)(b*HN + h)*W + i)*W + v ] = s;
}

// ---------------- fused online-softmax + AV; v-chunk 16, single-wave occupancy ----------
__global__ __launch_bounds__(128, 8)
void k_av(const float* __restrict__ attn, const float* __restrict__ kv,
          float* __restrict__ vo) {
    __shared__ float Ps[256*17];                 // stride 17: conflict-free scalar reads
    __shared__ __align__(16) float Vs[16*20];    // stride 20: aligned float4 broadcast reads
    int e = blockIdx.x, n = blockIdx.y;
    int t = threadIdx.x;     // 128: rows t and t+128
    float acc[2][16] = {};
    float m0 = -1e30f, m1 = -1e30f, s0 = 0.f, s1 = 0.f;
    const float* P = attn + (size_t)(n*NE + e)*W*W;
    for (int v0 = 0; v0 < W; v0 += 16) {
        __syncthreads();
        // stage P: 256 rows x 16 v
        #pragma unroll
        for (int k = 0; k < 32; k++) {
            int idx = t + k*128;
            int ii = idx >> 4, vv = idx & 15;
            Ps[ii*17 + vv] = P[(size_t)ii*W + v0 + vv];
        }
        // stage V: 16 rows x 16 cc as float4 (threads 0..63)
        if (t < 64) {
            int vv = t >> 2, cc4 = t & 3;
            float4 vx = *(const float4*)&kv[(size_t)((v0+vv)*NB + n)*(2*C) + C + e*16 + cc4*4];
            *(float4*)&Vs[vv*20 + cc4*4] = vx;
        }
        __syncthreads();
        float cm0 = -1e30f, cm1 = -1e30f;
        #pragma unroll
        for (int vv = 0; vv < 16; vv++) {
            cm0 = fmaxf(cm0, Ps[t*17 + vv]);
            cm1 = fmaxf(cm1, Ps[(t+128)*17 + vv]);
        }
        if (cm0 > m0) {
            float c = __expf(m0 - cm0);
            s0 *= c;
            #pragma unroll
            for (int cc = 0; cc < 16; cc++) acc[0][cc] *= c;
            m0 = cm0;
        }
        if (cm1 > m1) {
            float c = __expf(m1 - cm1);
            s1 *= c;
            #pragma unroll
            for (int cc = 0; cc < 16; cc++) acc[1][cc] *= c;
            m1 = cm1;
        }
        #pragma unroll 4
        for (int vv = 0; vv < 16; vv++) {
            float p0 = __expf(Ps[t*17 + vv] - m0);
            float p1 = __expf(Ps[(t+128)*17 + vv] - m1);
            s0 += p0; s1 += p1;
            #pragma unroll
            for (int c4 = 0; c4 < 4; c4++) {
                float4 vx = *(const float4*)&Vs[vv*20 + c4*4];
                acc[0][c4*4+0] += p0*vx.x; acc[0][c4*4+1] += p0*vx.y;
                acc[0][c4*4+2] += p0*vx.z; acc[0][c4*4+3] += p0*vx.w;
                acc[1][c4*4+0] += p1*vx.x; acc[1][c4*4+1] += p1*vx.y;
                acc[1][c4*4+2] += p1*vx.z; acc[1][c4*4+3] += p1*vx.w;
            }
        }
    }
    float inv0 = 1.0f/s0, inv1 = 1.0f/s1;
    {
        float4* dst = (float4*)&vo[(size_t)((size_t)t*NB + n)*C + e*16];
        dst[0] = make_float4(acc[0][0]*inv0, acc[0][1]*inv0, acc[0][2]*inv0, acc[0][3]*inv0);
        dst[1] = make_float4(acc[0][4]*inv0, acc[0][5]*inv0, acc[0][6]*inv0, acc[0][7]*inv0);
        dst[2] = make_float4(acc[0][8]*inv0, acc[0][9]*inv0, acc[0][10]*inv0, acc[0][11]*inv0);
        dst[3] = make_float4(acc[0][12]*inv0, acc[0][13]*inv0, acc[0][14]*inv0, acc[0][15]*inv0);
    }
    {
        float4* dst = (float4*)&vo[(size_t)((size_t)(t+128)*NB + n)*C + e*16];
        dst[0] = make_float4(acc[1][0]*inv1, acc[1][1]*inv1, acc[1][2]*inv1, acc[1][3]*inv1);
        dst[1] = make_float4(acc[1][4]*inv1, acc[1][5]*inv1, acc[1][6]*inv1, acc[1][7]*inv1);
        dst[2] = make_float4(acc[1][8]*inv1, acc[1][9]*inv1, acc[1][10]*inv1, acc[1][11]*inv1);
        dst[3] = make_float4(acc[1][12]*inv1, acc[1][13]*inv1, acc[1][14]*inv1, acc[1][15]*inv1);
    }
}

// ---------------- host ----------------
extern "C" void kernel_launch(void* const* d_in, const int* in_sizes, int n_in,
                              void* d_out, int out_size) {
    const float* feat_left  = (const float*)d_in[0];
    const float* feat_right = (const float*)d_in[1];
    const float* pos        = (const float*)d_in[2];
    // d_in[3] pos_indexes: analytic d = 255 +/- (i-v) used instead
    const float* Wqkv = (const float*)d_in[4];
    const float* bqkv = (const float*)d_in[5];
    const float* Wo   = (const float*)d_in[6];
    const float* bo   = (const float*)d_in[7];
    const float* g1   = (const float*)d_in[8];
    const float* b1   = (const float*)d_in[9];
    const float* g2   = (const float*)d_in[10];
    const float* b2   = (const float*)d_in[11];
    float* out = (float*)d_out;

    float *fl,*fr,*fl2,*fr2,*q,*kv,*qr,*kr,*attn;
    cudaGetSymbolAddress((void**)&fl,   g_fl);
    cudaGetSymbolAddress((void**)&fr,   g_fr);
    cudaGetSymbolAddress((void**)&fl2,  g_fl2);
    cudaGetSymbolAddress((void**)&fr2,  g_fr2);
    cudaGetSymbolAddress((void**)&q,    g_q);
    cudaGetSymbolAddress((void**)&kv,   g_kv);
    cudaGetSymbolAddress((void**)&qr,   g_qr);
    cudaGetSymbolAddress((void**)&kr,   g_kr);
    cudaGetSymbolAddress((void**)&attn, g_attn);
    float* vo = q;   // q dead after k_scores/k_rawsum; k_av may overwrite

    dim3 bt(32, 8);
    dim3 gt2(8, 4, 256);   // z = hb(128) * src(2)

    // to_seq (both) + LN(g1,b1) (both), z/y-batched
    k_reorder_in<<<gt2, bt>>>(feat_right, fr, feat_left, fl);
    k_layernorm2<<<dim3(ROWS,2), 128>>>(fr, fr2, fl, fl2, g1, b1);

    // all projections for MHA1 + positional tables, one z-batched launch
    k_gemm_qkv<<<dim3(512,1,5), 256>>>(fr2, fl2, pos, Wqkv, bqkv, q, kv, qr, kr);

    // MHA1: d = 255 - (i - v)
    k_scores<<<dim3(8, NE, NB), 256>>>(q, kv, qr, kr, attn, -1);
    k_av<<<dim3(NE, NB), 128>>>(attn, kv, vo);
    k_gemm<<<dim3(512,1), 256>>>(vo, Wo, bo, fr, fr, ROWS, 1.0f, 128);  // fr += upd_r

    // fr2 <- ln(fr, g2, b2)
    k_layernorm2<<<dim3(ROWS,1), 128>>>(fr, fr2, nullptr, nullptr, g2, b2);

    // MHA2: d = 255 + (i - v)
    k_gemm_qkv<<<dim3(512,1,3), 256>>>(fl2, fr2, pos, Wqkv, bqkv, q, kv, qr, kr);
    k_scores<<<dim3(8, NE, NB), 256>>>(q, kv, qr, kr, attn, +1);
    k_rawsum<<<dim3(W, NB), 256>>>(attn, out + 8388608);
    k_av<<<dim3(NE, NB), 128>>>(attn, kv, vo);
    k_gemm<<<dim3(512,1), 256>>>(vo, Wo, bo, fl, fl, ROWS, 1.0f, 128);  // fl += upd_l

    // from_seq (both)
    k_reorder_out<<<gt2, bt>>>(fl, out, fr, out + 4194304);
}

// round 12
// speedup vs baseline: 1.7447x; 1.7447x over previous
#include <cuda_runtime.h>
#include <cstdint>

#define W   256
#define NB  128     // n = hn*bs
#define C   128
#define NE  8       // heads
#define HD  16
#define D2  511     // 2W-1
#define ROWS (W*NB) // 32768
#define HN  64

// ---------------- scratch (device globals; no allocation) ----------------
__device__ float g_fl[ROWS*C];
__device__ float g_fr[ROWS*C];
__device__ float g_fl2[ROWS*C];
__device__ float g_fr2[ROWS*C];
__device__ float g_q[ROWS*C];          // reused as vo (q dead after k_scores/k_rawsum)
__device__ float g_kv[ROWS*2*C];
__device__ float g_qr[D2*C];
__device__ float g_kr[D2*C];
__device__ float g_attn[(size_t)NB*NE*W*W];   // raw scores, 268 MB

// ---------------- reorder in (z-batched over both inputs): (bs,c,hn,w) -> X[i][j][cc] ----
// gridDim.z = 256: hb = z & 127 (h = hb>>1 in [0,64), b = hb&1), s = z >> 7 selects tensor
__global__ void k_reorder_in(const float* __restrict__ inA, float* __restrict__ outA,
                             const float* __restrict__ inB, float* __restrict__ outB) {
    __shared__ float sm[32][33];
    int itile = blockIdx.x*32, cctile = blockIdx.y*32;
    int hb = blockIdx.z & 127, s = blockIdx.z >> 7;
    const float* in = s ? inB : inA;
    float* out = s ? outB : outA;
    int h = hb >> 1, b = hb & 1, j = h*2 + b;
    int tx = threadIdx.x, ty = threadIdx.y;
    #pragma unroll
    for (int r = 0; r < 32; r += 8) {
        int cc = cctile + r + ty;
        sm[r+ty][tx] = in[ ((b*C + cc)*HN + h)*W + itile + tx ];
    }
    __syncthreads();
    #pragma unroll
    for (int r = 0; r < 32; r += 8) {
        int i = itile + r + ty;
        out[ (i*NB + j)*C + cctile + tx ] = sm[tx][r+ty];
    }
}

// ---------------- reorder out (z-batched, same z mapping) ----------------
__global__ void k_reorder_out(const float* __restrict__ XA, float* __restrict__ outA,
                              const float* __restrict__ XB, float* __restrict__ outB) {
    __shared__ float sm[32][33];
    int itile = blockIdx.x*32, cctile = blockIdx.y*32;
    int hb = blockIdx.z & 127, s = blockIdx.z >> 7;
    const float* X = s ? XB : XA;
    float* out = s ? outB : outA;
    int h = hb >> 1, b = hb & 1, j = h*2 + b;
    int tx = threadIdx.x, ty = threadIdx.y;
    #pragma unroll
    for (int r = 0; r < 32; r += 8) {
        int i = itile + r + ty;
        sm[r+ty][tx] = X[ (i*NB + j)*C + cctile + tx ];
    }
    __syncthreads();
    #pragma unroll
    for (int r = 0; r < 32; r += 8) {
        int cc = cctile + r + ty;
        out[ ((b*C + cc)*HN + h)*W + itile + tx ] = sm[tx][r+ty];
    }
}

// ---------------- layernorm (optionally y-batched over two tensors) ----------------
__global__ void k_layernorm2(const float* __restrict__ XA, float* __restrict__ YA,
                             const float* __restrict__ XB, float* __restrict__ YB,
                             const float* __restrict__ g, const float* __restrict__ b) {
    int row = blockIdx.x;
    const float* X = blockIdx.y ? XB : XA;
    float* Y = blockIdx.y ? YB : YA;
    int t = threadIdx.x;
    float x = X[row*C + t];
    __shared__ float red[4];
    float s = x;
    #pragma unroll
    for (int o = 16; o; o >>= 1) s += __shfl_xor_sync(0xffffffffu, s, o);
    if ((t & 31) == 0) red[t >> 5] = s;
    __syncthreads();
    float mean = (red[0]+red[1]+red[2]+red[3]) * (1.0f/C);
    float d = x - mean;
    float s2 = d*d;
    #pragma unroll
    for (int o = 16; o; o >>= 1) s2 += __shfl_xor_sync(0xffffffffu, s2, o);
    __syncthreads();
    if ((t & 31) == 0) red[t >> 5] = s2;
    __syncthreads();
    float var = (red[0]+red[1]+red[2]+red[3]) * (1.0f/C);
    Y[row*C + t] = d * rsqrtf(var + 1e-5f) * g[t] + b[t];
}

// ---------------- GEMM tile body (64 rows x 128 cols, K=128 chunked by 32) ----------------
__device__ __forceinline__ void gemm_tile(const float* __restrict__ A, const float* __restrict__ Wr,
                                          const float* __restrict__ bias, const float* __restrict__ res,
                                          float* __restrict__ Cout, int M, float scale, int ldc,
                                          float* As, float* Bs) {
    int m0 = blockIdx.x*64;
    if (m0 >= M) return;
    int tid = threadIdx.x;
    int tx = tid & 15, ty = tid >> 4;
    float acc[4][8] = {};

    for (int kc = 0; kc < 128; kc += 32) {
        __syncthreads();
        #pragma unroll
        for (int rep = 0; rep < 2; rep++) {
            int f4 = tid + rep*256;
            int m = f4 >> 3, k4 = f4 & 7;
            int gm = m0 + m;
            float4 v = (gm < M) ? *(const float4*)&A[(size_t)gm*128 + kc + k4*4]
                                : make_float4(0.f,0.f,0.f,0.f);
            As[(4*k4+0)*68 + m] = v.x;
            As[(4*k4+1)*68 + m] = v.y;
            As[(4*k4+2)*68 + m] = v.z;
            As[(4*k4+3)*68 + m] = v.w;
        }
        #pragma unroll
        for (int rep = 0; rep < 4; rep++) {
            int f4 = tid + rep*256;
            int n = f4 >> 3, k4 = f4 & 7;
            float4 v = *(const float4*)&Wr[(size_t)n*128 + kc + k4*4];
            Bs[(4*k4+0)*132 + n] = v.x;
            Bs[(4*k4+1)*132 + n] = v.y;
            Bs[(4*k4+2)*132 + n] = v.z;
            Bs[(4*k4+3)*132 + n] = v.w;
        }
        __syncthreads();
        #pragma unroll
        for (int kk = 0; kk < 32; kk++) {
            float4 a  = *(float4*)&As[kk*68 + 4*ty];
            float4 b0 = *(float4*)&Bs[kk*132 + 4*tx];
            float4 b1 = *(float4*)&Bs[kk*132 + 64 + 4*tx];
            float av[4] = {a.x, a.y, a.z, a.w};
            float bv[8] = {b0.x, b0.y, b0.z, b0.w, b1.x, b1.y, b1.z, b1.w};
            #pragma unroll
            for (int r = 0; r < 4; r++)
                #pragma unroll
                for (int c = 0; c < 8; c++) acc[r][c] += av[r]*bv[c];
        }
    }

    float4 bi0 = *(const float4*)&bias[4*tx];
    float4 bi1 = *(const float4*)&bias[64 + 4*tx];
    float bb[8] = {bi0.x, bi0.y, bi0.z, bi0.w, bi1.x, bi1.y, bi1.z, bi1.w};
    #pragma unroll
    for (int r = 0; r < 4; r++) {
        int gm = m0 + 4*ty + r;
        if (gm >= M) continue;
        float o[8];
        #pragma unroll
        for (int c = 0; c < 8; c++) o[c] = scale * (acc[r][c] + bb[c]);
        size_t base = (size_t)gm*ldc;
        if (res) {
            float4 r0 = *(const float4*)&res[base + 4*tx];
            float4 r1 = *(const float4*)&res[base + 64 + 4*tx];
            o[0]+=r0.x; o[1]+=r0.y; o[2]+=r0.z; o[3]+=r0.w;
            o[4]+=r1.x; o[5]+=r1.y; o[6]+=r1.z; o[7]+=r1.w;
        }
        *(float4*)&Cout[base + 4*tx]      = make_float4(o[0],o[1],o[2],o[3]);
        *(float4*)&Cout[base + 64 + 4*tx] = make_float4(o[4],o[5],o[6],o[7]);
    }
}

__global__ __launch_bounds__(256, 4)
void k_gemm(const float* __restrict__ A, const float* __restrict__ Wr,
            const float* __restrict__ bias, const float* __restrict__ res,
            float* __restrict__ Cout, int M, float scale, int ldc) {
    __shared__ __align__(16) float As[32*68];
    __shared__ __align__(16) float Bs[32*132];
    gemm_tile(A, Wr, bias, res, Cout, M, scale, ldc, As, Bs);
}

// batched projections: z=0 q, z=1 K, z=2 V, z=3 qr, z=4 kr
__global__ __launch_bounds__(256, 4)
void k_gemm_qkv(const float* __restrict__ Aq, const float* __restrict__ Akv,
                const float* __restrict__ pos,
                const float* __restrict__ Wqkv, const float* __restrict__ bqkv,
                float* __restrict__ q, float* __restrict__ kv,
                float* __restrict__ qr, float* __restrict__ kr) {
    __shared__ __align__(16) float As[32*68];
    __shared__ __align__(16) float Bs[32*132];
    int z = blockIdx.z;
    switch (z) {
        case 0: gemm_tile(Aq,  Wqkv,           bqkv,     nullptr, q,      ROWS, 0.25f, 128, As, Bs); break;
        case 1: gemm_tile(Akv, Wqkv + 128*128, bqkv+128, nullptr, kv,     ROWS, 1.0f,  256, As, Bs); break;
        case 2: gemm_tile(Akv, Wqkv + 256*128, bqkv+256, nullptr, kv+128, ROWS, 1.0f,  256, As, Bs); break;
        case 3: gemm_tile(pos, Wqkv,           bqkv,     nullptr, qr,     D2,   0.25f, 128, As, Bs); break;
        case 4: gemm_tile(pos, Wqkv + 128*128, bqkv+128, nullptr, kr,     D2,   1.0f,  128, As, Bs); break;
    }
}

// ---------------- scores: attn[n,e,i,v] = q·k + q·kr[d] + qr[d]·k, d = 255+sgn*(i-v) ----
// cc-rotation per lane makes all smem reads (stride-17 arrays, lane-stride 4 rows)
// conflict-free: addr gains +ty -> bank stride 5 (odd) -> 16 distinct banks.
__global__ __launch_bounds__(256, 3)
void k_scores(const float* __restrict__ q, const float* __restrict__ kv,
              const float* __restrict__ qr, const float* __restrict__ kr,
              float* __restrict__ attn, int sgn) {
    __shared__ float Qs[64*17];
    __shared__ float Ks[128*17];
    __shared__ float QRs[192*17];
    __shared__ float KRs[192*17];
    int i0 = (blockIdx.x >> 1) * 64;
    int v0 = (blockIdx.x & 1) * 128;
    int e = blockIdx.y, n = blockIdx.z;
    int tid = threadIdx.x;
    int dmin = (sgn > 0) ? (128 + i0 - v0) : (192 - i0 + v0);
    for (int idx = tid; idx < 64*16; idx += 256) {
        int r = idx >> 4, cc = idx & 15;
        Qs[r*17+cc] = q[(size_t)((i0+r)*NB + n)*C + e*16 + cc];
    }
    for (int idx = tid; idx < 128*16; idx += 256) {
        int r = idx >> 4, cc = idx & 15;
        Ks[r*17+cc] = kv[(size_t)((v0+r)*NB + n)*(2*C) + e*16 + cc];
    }
    for (int idx = tid; idx < 192*16; idx += 256) {
        int r = idx >> 4, cc = idx & 15;
        QRs[r*17+cc] = qr[(dmin+r)*C + e*16 + cc];
        KRs[r*17+cc] = kr[(dmin+r)*C + e*16 + cc];
    }
    __syncthreads();
    int ty = tid & 15, tx = tid >> 4;
    int ib = ty*4, vb = tx*8;
    int ccr = tid & 15;                          // per-lane channel rotation
    int dbase = (sgn > 0) ? (127 + ib - vb) : (63 - ib + vb);
    int doff[11];
    #pragma unroll
    for (int k = 0; k < 11; k++) doff[k] = (dbase + sgn*(k - 7))*17;
    float acc[4][8] = {};
    #pragma unroll 2
    for (int cs = 0; cs < 16; cs++) {
        int cc = (cs + ccr) & 15;
        float qa[4], ka[8], qrl[11], krl[11];
        #pragma unroll
        for (int r = 0; r < 4; r++) qa[r] = Qs[(ib+r)*17 + cc];
        #pragma unroll
        for (int r = 0; r < 8; r++) ka[r] = Ks[(vb+r)*17 + cc];
        #pragma unroll
        for (int k = 0; k < 11; k++) { qrl[k] = QRs[doff[k] + cc]; krl[k] = KRs[doff[k] + cc]; }
        #pragma unroll
        for (int ri = 0; ri < 4; ri++)
            #pragma unroll
            for (int rv = 0; rv < 8; rv++) {
                int k = ri - rv + 7;
                acc[ri][rv] += qa[ri]*(ka[rv] + krl[k]) + qrl[k]*ka[rv];
            }
    }
    #pragma unroll
    for (int ri = 0; ri < 4; ri++) {
        int i = i0 + ib + ri;
        float4* dst = (float4*)&attn[ ((size_t)(n*NE + e)*W + i)*W + v0 + vb ];
        dst[0] = make_float4(acc[ri][0], acc[ri][1], acc[ri][2], acc[ri][3]);
        dst[1] = make_float4(acc[ri][4], acc[ri][5], acc[ri][6], acc[ri][7]);
    }
}

// ---------------- rawsum: rawout[(b,h),i,v] = sum_e attn[n,e,i,v] (memory-bound) --------
__global__ void k_rawsum(const float* __restrict__ attn, float* __restrict__ rawout) {
    int i = blockIdx.x, n = blockIdx.y;
    int v = threadIdx.x;   // 256
    const float* base = attn + ((size_t)(n*NE)*W + i)*W + v;
    float s = 0.f;
    #pragma unroll
    for (int e = 0; e < NE; e++) s += base[(size_t)e*W*W];
    int b = n & 1, h = n >> 1;
    rawout[ ((size_t)(b*HN + h)*W + i)*W + v ] = s;
}

// ---------------- fused online-softmax + AV; v-chunk 16, single-wave occupancy ----------
__global__ __launch_bounds__(128, 8)
void k_av(const float* __restrict__ attn, const float* __restrict__ kv,
          float* __restrict__ vo) {
    __shared__ float Ps[256*17];                 // stride 17: conflict-free scalar reads
    __shared__ __align__(16) float Vs[16*20];    // stride 20: aligned float4 broadcast reads
    int e = blockIdx.x, n = blockIdx.y;
    int t = threadIdx.x;     // 128: rows t and t+128
    float acc[2][16] = {};
    float m0 = -1e30f, m1 = -1e30f, s0 = 0.f, s1 = 0.f;
    const float* P = attn + (size_t)(n*NE + e)*W*W;
    for (int v0 = 0; v0 < W; v0 += 16) {
        __syncthreads();
        // stage P: 256 rows x 16 v
        #pragma unroll
        for (int k = 0; k < 32; k++) {
            int idx = t + k*128;
            int ii = idx >> 4, vv = idx & 15;
            Ps[ii*17 + vv] = P[(size_t)ii*W + v0 + vv];
        }
        // stage V: 16 rows x 16 cc as float4 (threads 0..63)
        if (t < 64) {
            int vv = t >> 2, cc4 = t & 3;
            float4 vx = *(const float4*)&kv[(size_t)((v0+vv)*NB + n)*(2*C) + C + e*16 + cc4*4];
            *(float4*)&Vs[vv*20 + cc4*4] = vx;
        }
        __syncthreads();
        float cm0 = -1e30f, cm1 = -1e30f;
        #pragma unroll
        for (int vv = 0; vv < 16; vv++) {
            cm0 = fmaxf(cm0, Ps[t*17 + vv]);
            cm1 = fmaxf(cm1, Ps[(t+128)*17 + vv]);
        }
        if (cm0 > m0) {
            float c = __expf(m0 - cm0);
            s0 *= c;
            #pragma unroll
            for (int cc = 0; cc < 16; cc++) acc[0][cc] *= c;
            m0 = cm0;
        }
        if (cm1 > m1) {
            float c = __expf(m1 - cm1);
            s1 *= c;
            #pragma unroll
            for (int cc = 0; cc < 16; cc++) acc[1][cc] *= c;
            m1 = cm1;
        }
        #pragma unroll 4
        for (int vv = 0; vv < 16; vv++) {
            float p0 = __expf(Ps[t*17 + vv] - m0);
            float p1 = __expf(Ps[(t+128)*17 + vv] - m1);
            s0 += p0; s1 += p1;
            #pragma unroll
            for (int c4 = 0; c4 < 4; c4++) {
                float4 vx = *(const float4*)&Vs[vv*20 + c4*4];
                acc[0][c4*4+0] += p0*vx.x; acc[0][c4*4+1] += p0*vx.y;
                acc[0][c4*4+2] += p0*vx.z; acc[0][c4*4+3] += p0*vx.w;
                acc[1][c4*4+0] += p1*vx.x; acc[1][c4*4+1] += p1*vx.y;
                acc[1][c4*4+2] += p1*vx.z; acc[1][c4*4+3] += p1*vx.w;
            }
        }
    }
    float inv0 = 1.0f/s0, inv1 = 1.0f/s1;
    {
        float4* dst = (float4*)&vo[(size_t)((size_t)t*NB + n)*C + e*16];
        dst[0] = make_float4(acc[0][0]*inv0, acc[0][1]*inv0, acc[0][2]*inv0, acc[0][3]*inv0);
        dst[1] = make_float4(acc[0][4]*inv0, acc[0][5]*inv0, acc[0][6]*inv0, acc[0][7]*inv0);
        dst[2] = make_float4(acc[0][8]*inv0, acc[0][9]*inv0, acc[0][10]*inv0, acc[0][11]*inv0);
        dst[3] = make_float4(acc[0][12]*inv0, acc[0][13]*inv0, acc[0][14]*inv0, acc[0][15]*inv0);
    }
    {
        float4* dst = (float4*)&vo[(size_t)((size_t)(t+128)*NB + n)*C + e*16];
        dst[0] = make_float4(acc[1][0]*inv1, acc[1][1]*inv1, acc[1][2]*inv1, acc[1][3]*inv1);
        dst[1] = make_float4(acc[1][4]*inv1, acc[1][5]*inv1, acc[1][6]*inv1, acc[1][7]*inv1);
        dst[2] = make_float4(acc[1][8]*inv1, acc[1][9]*inv1, acc[1][10]*inv1, acc[1][11]*inv1);
        dst[3] = make_float4(acc[1][12]*inv1, acc[1][13]*inv1, acc[1][14]*inv1, acc[1][15]*inv1);
    }
}

// ---------------- host ----------------
extern "C" void kernel_launch(void* const* d_in, const int* in_sizes, int n_in,
                              void* d_out, int out_size) {
    const float* feat_left  = (const float*)d_in[0];
    const float* feat_right = (const float*)d_in[1];
    const float* pos        = (const float*)d_in[2];
    // d_in[3] pos_indexes: analytic d = 255 +/- (i-v) used instead
    const float* Wqkv = (const float*)d_in[4];
    const float* bqkv = (const float*)d_in[5];
    const float* Wo   = (const float*)d_in[6];
    const float* bo   = (const float*)d_in[7];
    const float* g1   = (const float*)d_in[8];
    const float* b1   = (const float*)d_in[9];
    const float* g2   = (const float*)d_in[10];
    const float* b2   = (const float*)d_in[11];
    float* out = (float*)d_out;

    float *fl,*fr,*fl2,*fr2,*q,*kv,*qr,*kr,*attn;
    cudaGetSymbolAddress((void**)&fl,   g_fl);
    cudaGetSymbolAddress((void**)&fr,   g_fr);
    cudaGetSymbolAddress((void**)&fl2,  g_fl2);
    cudaGetSymbolAddress((void**)&fr2,  g_fr2);
    cudaGetSymbolAddress((void**)&q,    g_q);
    cudaGetSymbolAddress((void**)&kv,   g_kv);
    cudaGetSymbolAddress((void**)&qr,   g_qr);
    cudaGetSymbolAddress((void**)&kr,   g_kr);
    cudaGetSymbolAddress((void**)&attn, g_attn);
    float* vo = q;   // q dead after k_scores/k_rawsum; k_av may overwrite

    dim3 bt(32, 8);
    dim3 gt2(8, 4, 256);   // z = hb(128) * src(2)

    // to_seq (both) + LN(g1,b1) (both), z/y-batched
    k_reorder_in<<<gt2, bt>>>(feat_right, fr, feat_left, fl);
    k_layernorm2<<<dim3(ROWS,2), 128>>>(fr, fr2, fl, fl2, g1, b1);

    // all projections for MHA1 + positional tables, one z-batched launch
    k_gemm_qkv<<<dim3(512,1,5), 256>>>(fr2, fl2, pos, Wqkv, bqkv, q, kv, qr, kr);

    // MHA1: d = 255 - (i - v)
    k_scores<<<dim3(8, NE, NB), 256>>>(q, kv, qr, kr, attn, -1);
    k_av<<<dim3(NE, NB), 128>>>(attn, kv, vo);
    k_gemm<<<dim3(512,1), 256>>>(vo, Wo, bo, fr, fr, ROWS, 1.0f, 128);  // fr += upd_r

    // fr2 <- ln(fr, g2, b2)
    k_layernorm2<<<dim3(ROWS,1), 128>>>(fr, fr2, nullptr, nullptr, g2, b2);

    // MHA2: d = 255 + (i - v)
    k_gemm_qkv<<<dim3(512,1,3), 256>>>(fl2, fr2, pos, Wqkv, bqkv, q, kv, qr, kr);
    k_scores<<<dim3(8, NE, NB), 256>>>(q, kv, qr, kr, attn, +1);
    k_rawsum<<<dim3(W, NB), 256>>>(attn, out + 8388608);
    k_av<<<dim3(NE, NB), 128>>>(attn, kv, vo);
    k_gemm<<<dim3(512,1), 256>>>(vo, Wo, bo, fl, fl, ROWS, 1.0f, 128);  // fl += upd_l

    // from_seq (both)
    k_reorder_out<<<gt2, bt>>>(fl, out, fr, out + 4194304);
}

// round 13
// speedup vs baseline: 1.7495x; 1.0028x over previous
#include <cuda_runtime.h>
#include <cstdint>

#define W   256
#define NB  128     // n = hn*bs
#define C   128
#define NE  8       // heads
#define HD  16
#define D2  511     // 2W-1
#define ROWS (W*NB) // 32768
#define HN  64

// ---------------- scratch (device globals; no allocation) ----------------
__device__ float g_fl[ROWS*C];
__device__ float g_fr[ROWS*C];
__device__ float g_fl2[ROWS*C];
__device__ float g_fr2[ROWS*C];
__device__ float g_q[ROWS*C];          // reused as vo (q dead after k_scores/k_rawsum)
__device__ float g_kv[ROWS*2*C];
__device__ float g_qr[D2*C];
__device__ float g_kr[D2*C];
__device__ float g_attn[(size_t)NB*NE*W*W];   // raw scores, 268 MB

// ---------------- reorder in (z-batched over both inputs): (bs,c,hn,w) -> X[i][j][cc] ----
__global__ void k_reorder_in(const float* __restrict__ inA, float* __restrict__ outA,
                             const float* __restrict__ inB, float* __restrict__ outB) {
    __shared__ float sm[32][33];
    int itile = blockIdx.x*32, cctile = blockIdx.y*32;
    int hb = blockIdx.z & 127, s = blockIdx.z >> 7;
    const float* in = s ? inB : inA;
    float* out = s ? outB : outA;
    int h = hb >> 1, b = hb & 1, j = h*2 + b;
    int tx = threadIdx.x, ty = threadIdx.y;
    #pragma unroll
    for (int r = 0; r < 32; r += 8) {
        int cc = cctile + r + ty;
        sm[r+ty][tx] = in[ ((b*C + cc)*HN + h)*W + itile + tx ];
    }
    __syncthreads();
    #pragma unroll
    for (int r = 0; r < 32; r += 8) {
        int i = itile + r + ty;
        out[ (i*NB + j)*C + cctile + tx ] = sm[tx][r+ty];
    }
}

// ---------------- reorder out (z-batched, same z mapping) ----------------
__global__ void k_reorder_out(const float* __restrict__ XA, float* __restrict__ outA,
                              const float* __restrict__ XB, float* __restrict__ outB) {
    __shared__ float sm[32][33];
    int itile = blockIdx.x*32, cctile = blockIdx.y*32;
    int hb = blockIdx.z & 127, s = blockIdx.z >> 7;
    const float* X = s ? XB : XA;
    float* out = s ? outB : outA;
    int h = hb >> 1, b = hb & 1, j = h*2 + b;
    int tx = threadIdx.x, ty = threadIdx.y;
    #pragma unroll
    for (int r = 0; r < 32; r += 8) {
        int i = itile + r + ty;
        sm[r+ty][tx] = X[ (i*NB + j)*C + cctile + tx ];
    }
    __syncthreads();
    #pragma unroll
    for (int r = 0; r < 32; r += 8) {
        int cc = cctile + r + ty;
        out[ ((b*C + cc)*HN + h)*W + itile + tx ] = sm[tx][r+ty];
    }
}

// ---------------- layernorm (optionally y-batched over two tensors) ----------------
__global__ void k_layernorm2(const float* __restrict__ XA, float* __restrict__ YA,
                             const float* __restrict__ XB, float* __restrict__ YB,
                             const float* __restrict__ g, const float* __restrict__ b) {
    int row = blockIdx.x;
    const float* X = blockIdx.y ? XB : XA;
    float* Y = blockIdx.y ? YB : YA;
    int t = threadIdx.x;
    float x = X[row*C + t];
    __shared__ float red[4];
    float s = x;
    #pragma unroll
    for (int o = 16; o; o >>= 1) s += __shfl_xor_sync(0xffffffffu, s, o);
    if ((t & 31) == 0) red[t >> 5] = s;
    __syncthreads();
    float mean = (red[0]+red[1]+red[2]+red[3]) * (1.0f/C);
    float d = x - mean;
    float s2 = d*d;
    #pragma unroll
    for (int o = 16; o; o >>= 1) s2 += __shfl_xor_sync(0xffffffffu, s2, o);
    __syncthreads();
    if ((t & 31) == 0) red[t >> 5] = s2;
    __syncthreads();
    float var = (red[0]+red[1]+red[2]+red[3]) * (1.0f/C);
    Y[row*C + t] = d * rsqrtf(var + 1e-5f) * g[t] + b[t];
}

// ---------------- GEMM tile body (64 rows x 128 cols, K=128 chunked by 32) ----------------
__device__ __forceinline__ void gemm_tile(const float* __restrict__ A, const float* __restrict__ Wr,
                                          const float* __restrict__ bias, const float* __restrict__ res,
                                          float* __restrict__ Cout, int M, float scale, int ldc,
                                          float* As, float* Bs) {
    int m0 = blockIdx.x*64;
    if (m0 >= M) return;
    int tid = threadIdx.x;
    int tx = tid & 15, ty = tid >> 4;
    float acc[4][8] = {};

    for (int kc = 0; kc < 128; kc += 32) {
        __syncthreads();
        #pragma unroll
        for (int rep = 0; rep < 2; rep++) {
            int f4 = tid + rep*256;
            int m = f4 >> 3, k4 = f4 & 7;
            int gm = m0 + m;
            float4 v = (gm < M) ? *(const float4*)&A[(size_t)gm*128 + kc + k4*4]
                                : make_float4(0.f,0.f,0.f,0.f);
            As[(4*k4+0)*68 + m] = v.x;
            As[(4*k4+1)*68 + m] = v.y;
            As[(4*k4+2)*68 + m] = v.z;
            As[(4*k4+3)*68 + m] = v.w;
        }
        #pragma unroll
        for (int rep = 0; rep < 4; rep++) {
            int f4 = tid + rep*256;
            int n = f4 >> 3, k4 = f4 & 7;
            float4 v = *(const float4*)&Wr[(size_t)n*128 + kc + k4*4];
            Bs[(4*k4+0)*132 + n] = v.x;
            Bs[(4*k4+1)*132 + n] = v.y;
            Bs[(4*k4+2)*132 + n] = v.z;
            Bs[(4*k4+3)*132 + n] = v.w;
        }
        __syncthreads();
        #pragma unroll
        for (int kk = 0; kk < 32; kk++) {
            float4 a  = *(float4*)&As[kk*68 + 4*ty];
            float4 b0 = *(float4*)&Bs[kk*132 + 4*tx];
            float4 b1 = *(float4*)&Bs[kk*132 + 64 + 4*tx];
            float av[4] = {a.x, a.y, a.z, a.w};
            float bv[8] = {b0.x, b0.y, b0.z, b0.w, b1.x, b1.y, b1.z, b1.w};
            #pragma unroll
            for (int r = 0; r < 4; r++)
                #pragma unroll
                for (int c = 0; c < 8; c++) acc[r][c] += av[r]*bv[c];
        }
    }

    float4 bi0 = *(const float4*)&bias[4*tx];
    float4 bi1 = *(const float4*)&bias[64 + 4*tx];
    float bb[8] = {bi0.x, bi0.y, bi0.z, bi0.w, bi1.x, bi1.y, bi1.z, bi1.w};
    #pragma unroll
    for (int r = 0; r < 4; r++) {
        int gm = m0 + 4*ty + r;
        if (gm >= M) continue;
        float o[8];
        #pragma unroll
        for (int c = 0; c < 8; c++) o[c] = scale * (acc[r][c] + bb[c]);
        size_t base = (size_t)gm*ldc;
        if (res) {
            float4 r0 = *(const float4*)&res[base + 4*tx];
            float4 r1 = *(const float4*)&res[base + 64 + 4*tx];
            o[0]+=r0.x; o[1]+=r0.y; o[2]+=r0.z; o[3]+=r0.w;
            o[4]+=r1.x; o[5]+=r1.y; o[6]+=r1.z; o[7]+=r1.w;
        }
        *(float4*)&Cout[base + 4*tx]      = make_float4(o[0],o[1],o[2],o[3]);
        *(float4*)&Cout[base + 64 + 4*tx] = make_float4(o[4],o[5],o[6],o[7]);
    }
}

__global__ __launch_bounds__(256, 4)
void k_gemm(const float* __restrict__ A, const float* __restrict__ Wr,
            const float* __restrict__ bias, const float* __restrict__ res,
            float* __restrict__ Cout, int M, float scale, int ldc) {
    __shared__ __align__(16) float As[32*68];
    __shared__ __align__(16) float Bs[32*132];
    gemm_tile(A, Wr, bias, res, Cout, M, scale, ldc, As, Bs);
}

// batched projections: z=0 q, z=1 K, z=2 V, z=3 qr, z=4 kr
__global__ __launch_bounds__(256, 4)
void k_gemm_qkv(const float* __restrict__ Aq, const float* __restrict__ Akv,
                const float* __restrict__ pos,
                const float* __restrict__ Wqkv, const float* __restrict__ bqkv,
                float* __restrict__ q, float* __restrict__ kv,
                float* __restrict__ qr, float* __restrict__ kr) {
    __shared__ __align__(16) float As[32*68];
    __shared__ __align__(16) float Bs[32*132];
    int z = blockIdx.z;
    switch (z) {
        case 0: gemm_tile(Aq,  Wqkv,           bqkv,     nullptr, q,      ROWS, 0.25f, 128, As, Bs); break;
        case 1: gemm_tile(Akv, Wqkv + 128*128, bqkv+128, nullptr, kv,     ROWS, 1.0f,  256, As, Bs); break;
        case 2: gemm_tile(Akv, Wqkv + 256*128, bqkv+256, nullptr, kv+128, ROWS, 1.0f,  256, As, Bs); break;
        case 3: gemm_tile(pos, Wqkv,           bqkv,     nullptr, qr,     D2,   0.25f, 128, As, Bs); break;
        case 4: gemm_tile(pos, Wqkv + 128*128, bqkv+128, nullptr, kr,     D2,   1.0f,  128, As, Bs); break;
    }
}

// ---------------- scores v3: tile 64i x 256v, micro 8x8, diagonal-k accumulation ----------
// SGN compile-time -> window addressing folds to immediate LDS offsets.
// cc-rotation keeps stride-17 smem reads conflict-free.
#define SCORES_SMEM ((64 + 256 + 320 + 320) * 17 * 4)
template<int SGN>
__global__ __launch_bounds__(256, 2)
void k_scores(const float* __restrict__ q, const float* __restrict__ kv,
              const float* __restrict__ qr, const float* __restrict__ kr,
              float* __restrict__ attn) {
    extern __shared__ float sm[];
    float* Qs  = sm;               // [64][17]
    float* Ks  = Qs + 64*17;       // [256][17]
    float* QRs = Ks + 256*17;      // [320][17]
    float* KRs = QRs + 320*17;     // [320][17]
    int i0 = blockIdx.x * 64;
    int e = blockIdx.y, n = blockIdx.z;
    int tid = threadIdx.x;
    int dmin = (SGN > 0) ? i0 : (192 - i0);   // 319-row window
    for (int idx = tid; idx < 64*16; idx += 256) {
        int r = idx >> 4, cc = idx & 15;
        Qs[r*17+cc] = q[(size_t)((i0+r)*NB + n)*C + e*16 + cc];
    }
    for (int idx = tid; idx < 256*16; idx += 256) {
        int r = idx >> 4, cc = idx & 15;
        Ks[r*17+cc] = kv[(size_t)(r*NB + n)*(2*C) + e*16 + cc];
    }
    for (int idx = tid; idx < 319*16; idx += 256) {
        int r = idx >> 4, cc = idx & 15;
        QRs[r*17+cc] = qr[(dmin+r)*C + e*16 + cc];
        KRs[r*17+cc] = kr[(dmin+r)*C + e*16 + cc];
    }
    __syncthreads();
    int ty = tid & 7, tx = tid >> 3;       // 8 i-groups x 32 v-groups
    int ib = ty*8, vb = tx*8;
    int ccr = tid & 15;
    // local window base (k=0 end): SGN+: dbase-7 ; SGN-: dbase+7, stepping by SGN
    int dstart = (SGN > 0) ? (255 + ib - vb - 7) : (63 - ib + vb + 7);
    float acc[8][8] = {};
    #pragma unroll 2
    for (int cs = 0; cs < 16; cs++) {
        int cc = (cs + ccr) & 15;
        const float* qp = &QRs[dstart*17 + cc];
        const float* kp = &KRs[dstart*17 + cc];
        float qa[8], ka[8];
        #pragma unroll
        for (int r = 0; r < 8; r++) qa[r] = Qs[(ib+r)*17 + cc];
        #pragma unroll
        for (int r = 0; r < 8; r++) ka[r] = Ks[(vb+r)*17 + cc];
        #pragma unroll
        for (int k = 0; k < 15; k++) {
            float qrk = qp[SGN*k*17];
            float krk = kp[SGN*k*17];
            #pragma unroll
            for (int rv = 0; rv < 8; rv++) {
                int ri = rv + k - 7;
                if (ri < 0 || ri > 7) continue;
                acc[ri][rv] += qa[ri]*(ka[rv] + krk) + qrk*ka[rv];
            }
        }
    }
    #pragma unroll
    for (int ri = 0; ri < 8; ri++) {
        int i = i0 + ib + ri;
        float4* dst = (float4*)&attn[ ((size_t)(n*NE + e)*W + i)*W + vb ];
        dst[0] = make_float4(acc[ri][0], acc[ri][1], acc[ri][2], acc[ri][3]);
        dst[1] = make_float4(acc[ri][4], acc[ri][5], acc[ri][6], acc[ri][7]);
    }
}

// ---------------- rawsum: rawout[(b,h),i,v] = sum_e attn[n,e,i,v] (memory-bound) --------
__global__ void k_rawsum(const float* __restrict__ attn, float* __restrict__ rawout) {
    int i = blockIdx.x, n = blockIdx.y;
    int v = threadIdx.x;   // 256
    const float* base = attn + ((size_t)(n*NE)*W + i)*W + v;
    float s = 0.f;
    #pragma unroll
    for (int e = 0; e < NE; e++) s += base[(size_t)e*W*W];
    int b = n & 1, h = n >> 1;
    rawout[ ((size_t)(b*HN + h)*W + i)*W + v ] = s;
}

// ---------------- fused online-softmax + AV; v-chunk 16, single-wave occupancy ----------
__global__ __launch_bounds__(128, 8)
void k_av(const float* __restrict__ attn, const float* __restrict__ kv,
          float* __restrict__ vo) {
    __shared__ float Ps[256*17];                 // stride 17: conflict-free scalar reads
    __shared__ __align__(16) float Vs[16*20];    // stride 20: aligned float4 broadcast reads
    int e = blockIdx.x, n = blockIdx.y;
    int t = threadIdx.x;     // 128: rows t and t+128
    float acc[2][16] = {};
    float m0 = -1e30f, m1 = -1e30f, s0 = 0.f, s1 = 0.f;
    const float* P = attn + (size_t)(n*NE + e)*W*W;
    for (int v0 = 0; v0 < W; v0 += 16) {
        __syncthreads();
        #pragma unroll
        for (int k = 0; k < 32; k++) {
            int idx = t + k*128;
            int ii = idx >> 4, vv = idx & 15;
            Ps[ii*17 + vv] = P[(size_t)ii*W + v0 + vv];
        }
        if (t < 64) {
            int vv = t >> 2, cc4 = t & 3;
            float4 vx = *(const float4*)&kv[(size_t)((v0+vv)*NB + n)*(2*C) + C + e*16 + cc4*4];
            *(float4*)&Vs[vv*20 + cc4*4] = vx;
        }
        __syncthreads();
        float cm0 = -1e30f, cm1 = -1e30f;
        #pragma unroll
        for (int vv = 0; vv < 16; vv++) {
            cm0 = fmaxf(cm0, Ps[t*17 + vv]);
            cm1 = fmaxf(cm1, Ps[(t+128)*17 + vv]);
        }
        if (cm0 > m0) {
            float c = __expf(m0 - cm0);
            s0 *= c;
            #pragma unroll
            for (int cc = 0; cc < 16; cc++) acc[0][cc] *= c;
            m0 = cm0;
        }
        if (cm1 > m1) {
            float c = __expf(m1 - cm1);
            s1 *= c;
            #pragma unroll
            for (int cc = 0; cc < 16; cc++) acc[1][cc] *= c;
            m1 = cm1;
        }
        #pragma unroll 4
        for (int vv = 0; vv < 16; vv++) {
            float p0 = __expf(Ps[t*17 + vv] - m0);
            float p1 = __expf(Ps[(t+128)*17 + vv] - m1);
            s0 += p0; s1 += p1;
            #pragma unroll
            for (int c4 = 0; c4 < 4; c4++) {
                float4 vx = *(const float4*)&Vs[vv*20 + c4*4];
                acc[0][c4*4+0] += p0*vx.x; acc[0][c4*4+1] += p0*vx.y;
                acc[0][c4*4+2] += p0*vx.z; acc[0][c4*4+3] += p0*vx.w;
                acc[1][c4*4+0] += p1*vx.x; acc[1][c4*4+1] += p1*vx.y;
                acc[1][c4*4+2] += p1*vx.z; acc[1][c4*4+3] += p1*vx.w;
            }
        }
    }
    float inv0 = 1.0f/s0, inv1 = 1.0f/s1;
    {
        float4* dst = (float4*)&vo[(size_t)((size_t)t*NB + n)*C + e*16];
        dst[0] = make_float4(acc[0][0]*inv0, acc[0][1]*inv0, acc[0][2]*inv0, acc[0][3]*inv0);
        dst[1] = make_float4(acc[0][4]*inv0, acc[0][5]*inv0, acc[0][6]*inv0, acc[0][7]*inv0);
        dst[2] = make_float4(acc[0][8]*inv0, acc[0][9]*inv0, acc[0][10]*inv0, acc[0][11]*inv0);
        dst[3] = make_float4(acc[0][12]*inv0, acc[0][13]*inv0, acc[0][14]*inv0, acc[0][15]*inv0);
    }
    {
        float4* dst = (float4*)&vo[(size_t)((size_t)(t+128)*NB + n)*C + e*16];
        dst[0] = make_float4(acc[1][0]*inv1, acc[1][1]*inv1, acc[1][2]*inv1, acc[1][3]*inv1);
        dst[1] = make_float4(acc[1][4]*inv1, acc[1][5]*inv1, acc[1][6]*inv1, acc[1][7]*inv1);
        dst[2] = make_float4(acc[1][8]*inv1, acc[1][9]*inv1, acc[1][10]*inv1, acc[1][11]*inv1);
        dst[3] = make_float4(acc[1][12]*inv1, acc[1][13]*inv1, acc[1][14]*inv1, acc[1][15]*inv1);
    }
}

// ---------------- host ----------------
extern "C" void kernel_launch(void* const* d_in, const int* in_sizes, int n_in,
                              void* d_out, int out_size) {
    const float* feat_left  = (const float*)d_in[0];
    const float* feat_right = (const float*)d_in[1];
    const float* pos        = (const float*)d_in[2];
    // d_in[3] pos_indexes: analytic d = 255 +/- (i-v) used instead
    const float* Wqkv = (const float*)d_in[4];
    const float* bqkv = (const float*)d_in[5];
    const float* Wo   = (const float*)d_in[6];
    const float* bo   = (const float*)d_in[7];
    const float* g1   = (const float*)d_in[8];
    const float* b1   = (const float*)d_in[9];
    const float* g2   = (const float*)d_in[10];
    const float* b2   = (const float*)d_in[11];
    float* out = (float*)d_out;

    float *fl,*fr,*fl2,*fr2,*q,*kv,*qr,*kr,*attn;
    cudaGetSymbolAddress((void**)&fl,   g_fl);
    cudaGetSymbolAddress((void**)&fr,   g_fr);
    cudaGetSymbolAddress((void**)&fl2,  g_fl2);
    cudaGetSymbolAddress((void**)&fr2,  g_fr2);
    cudaGetSymbolAddress((void**)&q,    g_q);
    cudaGetSymbolAddress((void**)&kv,   g_kv);
    cudaGetSymbolAddress((void**)&qr,   g_qr);
    cudaGetSymbolAddress((void**)&kr,   g_kr);
    cudaGetSymbolAddress((void**)&attn, g_attn);
    float* vo = q;   // q dead after k_scores/k_rawsum; k_av may overwrite

    cudaFuncSetAttribute(k_scores<1>,  cudaFuncAttributeMaxDynamicSharedMemorySize, SCORES_SMEM);
    cudaFuncSetAttribute(k_scores<-1>, cudaFuncAttributeMaxDynamicSharedMemorySize, SCORES_SMEM);

    dim3 bt(32, 8);
    dim3 gt2(8, 4, 256);   // z = hb(128) * src(2)

    // to_seq (both) + LN(g1,b1) (both)
    k_reorder_in<<<gt2, bt>>>(feat_right, fr, feat_left, fl);
    k_layernorm2<<<dim3(ROWS,2), 128>>>(fr, fr2, fl, fl2, g1, b1);

    // all projections for MHA1 + positional tables, one z-batched launch
    k_gemm_qkv<<<dim3(512,1,5), 256>>>(fr2, fl2, pos, Wqkv, bqkv, q, kv, qr, kr);

    // MHA1: d = 255 - (i - v)
    k_scores<-1><<<dim3(4, NE, NB), 256, SCORES_SMEM>>>(q, kv, qr, kr, attn);
    k_av<<<dim3(NE, NB), 128>>>(attn, kv, vo);
    k_gemm<<<dim3(512,1), 256>>>(vo, Wo, bo, fr, fr, ROWS, 1.0f, 128);  // fr += upd_r

    // fr2 <- ln(fr, g2, b2)
    k_layernorm2<<<dim3(ROWS,1), 128>>>(fr, fr2, nullptr, nullptr, g2, b2);

    // MHA2: d = 255 + (i - v)
    k_gemm_qkv<<<dim3(512,1,3), 256>>>(fl2, fr2, pos, Wqkv, bqkv, q, kv, qr, kr);
    k_scores<1><<<dim3(4, NE, NB), 256, SCORES_SMEM>>>(q, kv, qr, kr, attn);
    k_rawsum<<<dim3(W, NB), 256>>>(attn, out + 8388608);
    k_av<<<dim3(NE, NB), 128>>>(attn, kv, vo);
    k_gemm<<<dim3(512,1), 256>>>(vo, Wo, bo, fl, fl, ROWS, 1.0f, 128);  // fl += upd_l

    // from_seq (both)
    k_reorder_out<<<gt2, bt>>>(fl, out, fr, out + 4194304);
}

// round 15
// speedup vs baseline: 1.9374x; 1.1074x over previous
#include <cuda_runtime.h>
#include <cstdint>

#define W   256
#define NB  128     // n = hn*bs
#define C   128
#define NE  8       // heads
#define HD  16
#define D2  511     // 2W-1
#define ROWS (W*NB) // 32768
#define HN  64

// ---------------- scratch (device globals; no allocation) ----------------
__device__ float g_fl[ROWS*C];
__device__ float g_fr[ROWS*C];
__device__ float g_fl2[ROWS*C];
__device__ float g_fr2[ROWS*C];
__device__ float g_q[ROWS*C];          // reused as vo (q dead after k_scores/k_rawsum)
__device__ float g_kv[ROWS*2*C];
__device__ float g_qr[D2*C];
__device__ float g_kr[D2*C];
__device__ float g_attn[(size_t)NB*NE*W*W];   // raw scores, 268 MB

// ---------------- reorder in (z-batched over both inputs): (bs,c,hn,w) -> X[i][j][cc] ----
__global__ void k_reorder_in(const float* __restrict__ inA, float* __restrict__ outA,
                             const float* __restrict__ inB, float* __restrict__ outB) {
    __shared__ float sm[32][33];
    int itile = blockIdx.x*32, cctile = blockIdx.y*32;
    int hb = blockIdx.z & 127, s = blockIdx.z >> 7;
    const float* in = s ? inB : inA;
    float* out = s ? outB : outA;
    int h = hb >> 1, b = hb & 1, j = h*2 + b;
    int tx = threadIdx.x, ty = threadIdx.y;
    #pragma unroll
    for (int r = 0; r < 32; r += 8) {
        int cc = cctile + r + ty;
        sm[r+ty][tx] = in[ ((b*C + cc)*HN + h)*W + itile + tx ];
    }
    __syncthreads();
    #pragma unroll
    for (int r = 0; r < 32; r += 8) {
        int i = itile + r + ty;
        out[ (i*NB + j)*C + cctile + tx ] = sm[tx][r+ty];
    }
}

// ---------------- reorder out (z-batched, same z mapping) ----------------
__global__ void k_reorder_out(const float* __restrict__ XA, float* __restrict__ outA,
                              const float* __restrict__ XB, float* __restrict__ outB) {
    __shared__ float sm[32][33];
    int itile = blockIdx.x*32, cctile = blockIdx.y*32;
    int hb = blockIdx.z & 127, s = blockIdx.z >> 7;
    const float* X = s ? XB : XA;
    float* out = s ? outB : outA;
    int h = hb >> 1, b = hb & 1, j = h*2 + b;
    int tx = threadIdx.x, ty = threadIdx.y;
    #pragma unroll
    for (int r = 0; r < 32; r += 8) {
        int i = itile + r + ty;
        sm[r+ty][tx] = X[ (i*NB + j)*C + cctile + tx ];
    }
    __syncthreads();
    #pragma unroll
    for (int r = 0; r < 32; r += 8) {
        int cc = cctile + r + ty;
        out[ ((b*C + cc)*HN + h)*W + itile + tx ] = sm[tx][r+ty];
    }
}

// ---------------- layernorm (optionally y-batched over two tensors) ----------------
__global__ void k_layernorm2(const float* __restrict__ XA, float* __restrict__ YA,
                             const float* __restrict__ XB, float* __restrict__ YB,
                             const float* __restrict__ g, const float* __restrict__ b) {
    int row = blockIdx.x;
    const float* X = blockIdx.y ? XB : XA;
    float* Y = blockIdx.y ? YB : YA;
    int t = threadIdx.x;
    float x = X[row*C + t];
    __shared__ float red[4];
    float s = x;
    #pragma unroll
    for (int o = 16; o; o >>= 1) s += __shfl_xor_sync(0xffffffffu, s, o);
    if ((t & 31) == 0) red[t >> 5] = s;
    __syncthreads();
    float mean = (red[0]+red[1]+red[2]+red[3]) * (1.0f/C);
    float d = x - mean;
    float s2 = d*d;
    #pragma unroll
    for (int o = 16; o; o >>= 1) s2 += __shfl_xor_sync(0xffffffffu, s2, o);
    __syncthreads();
    if ((t & 31) == 0) red[t >> 5] = s2;
    __syncthreads();
    float var = (red[0]+red[1]+red[2]+red[3]) * (1.0f/C);
    Y[row*C + t] = d * rsqrtf(var + 1e-5f) * g[t] + b[t];
}

// ---------------- GEMM tile body (64 rows x 128 cols, K=128 chunked by 32) ----------------
__device__ __forceinline__ void gemm_tile(const float* __restrict__ A, const float* __restrict__ Wr,
                                          const float* __restrict__ bias, const float* __restrict__ res,
                                          float* __restrict__ Cout, int M, float scale, int ldc,
                                          float* As, float* Bs) {
    int m0 = blockIdx.x*64;
    if (m0 >= M) return;
    int tid = threadIdx.x;
    int tx = tid & 15, ty = tid >> 4;
    float acc[4][8] = {};

    for (int kc = 0; kc < 128; kc += 32) {
        __syncthreads();
        #pragma unroll
        for (int rep = 0; rep < 2; rep++) {
            int f4 = tid + rep*256;
            int m = f4 >> 3, k4 = f4 & 7;
            int gm = m0 + m;
            float4 v = (gm < M) ? *(const float4*)&A[(size_t)gm*128 + kc + k4*4]
                                : make_float4(0.f,0.f,0.f,0.f);
            As[(4*k4+0)*68 + m] = v.x;
            As[(4*k4+1)*68 + m] = v.y;
            As[(4*k4+2)*68 + m] = v.z;
            As[(4*k4+3)*68 + m] = v.w;
        }
        #pragma unroll
        for (int rep = 0; rep < 4; rep++) {
            int f4 = tid + rep*256;
            int n = f4 >> 3, k4 = f4 & 7;
            float4 v = *(const float4*)&Wr[(size_t)n*128 + kc + k4*4];
            Bs[(4*k4+0)*132 + n] = v.x;
            Bs[(4*k4+1)*132 + n] = v.y;
            Bs[(4*k4+2)*132 + n] = v.z;
            Bs[(4*k4+3)*132 + n] = v.w;
        }
        __syncthreads();
        #pragma unroll
        for (int kk = 0; kk < 32; kk++) {
            float4 a  = *(float4*)&As[kk*68 + 4*ty];
            float4 b0 = *(float4*)&Bs[kk*132 + 4*tx];
            float4 b1 = *(float4*)&Bs[kk*132 + 64 + 4*tx];
            float av[4] = {a.x, a.y, a.z, a.w};
            float bv[8] = {b0.x, b0.y, b0.z, b0.w, b1.x, b1.y, b1.z, b1.w};
            #pragma unroll
            for (int r = 0; r < 4; r++)
                #pragma unroll
                for (int c = 0; c < 8; c++) acc[r][c] += av[r]*bv[c];
        }
    }

    float4 bi0 = *(const float4*)&bias[4*tx];
    float4 bi1 = *(const float4*)&bias[64 + 4*tx];
    float bb[8] = {bi0.x, bi0.y, bi0.z, bi0.w, bi1.x, bi1.y, bi1.z, bi1.w};
    #pragma unroll
    for (int r = 0; r < 4; r++) {
        int gm = m0 + 4*ty + r;
        if (gm >= M) continue;
        float o[8];
        #pragma unroll
        for (int c = 0; c < 8; c++) o[c] = scale * (acc[r][c] + bb[c]);
        size_t base = (size_t)gm*ldc;
        if (res) {
            float4 r0 = *(const float4*)&res[base + 4*tx];
            float4 r1 = *(const float4*)&res[base + 64 + 4*tx];
            o[0]+=r0.x; o[1]+=r0.y; o[2]+=r0.z; o[3]+=r0.w;
            o[4]+=r1.x; o[5]+=r1.y; o[6]+=r1.z; o[7]+=r1.w;
        }
        *(float4*)&Cout[base + 4*tx]      = make_float4(o[0],o[1],o[2],o[3]);
        *(float4*)&Cout[base + 64 + 4*tx] = make_float4(o[4],o[5],o[6],o[7]);
    }
}

__global__ __launch_bounds__(256, 4)
void k_gemm(const float* __restrict__ A, const float* __restrict__ Wr,
            const float* __restrict__ bias, const float* __restrict__ res,
            float* __restrict__ Cout, int M, float scale, int ldc) {
    __shared__ __align__(16) float As[32*68];
    __shared__ __align__(16) float Bs[32*132];
    gemm_tile(A, Wr, bias, res, Cout, M, scale, ldc, As, Bs);
}

// batched projections: z=0 q, z=1 K, z=2 V, z=3 qr, z=4 kr
__global__ __launch_bounds__(256, 4)
void k_gemm_qkv(const float* __restrict__ Aq, const float* __restrict__ Akv,
                const float* __restrict__ pos,
                const float* __restrict__ Wqkv, const float* __restrict__ bqkv,
                float* __restrict__ q, float* __restrict__ kv,
                float* __restrict__ qr, float* __restrict__ kr) {
    __shared__ __align__(16) float As[32*68];
    __shared__ __align__(16) float Bs[32*132];
    int z = blockIdx.z;
    switch (z) {
        case 0: gemm_tile(Aq,  Wqkv,           bqkv,     nullptr, q,      ROWS, 0.25f, 128, As, Bs); break;
        case 1: gemm_tile(Akv, Wqkv + 128*128, bqkv+128, nullptr, kv,     ROWS, 1.0f,  256, As, Bs); break;
        case 2: gemm_tile(Akv, Wqkv + 256*128, bqkv+256, nullptr, kv+128, ROWS, 1.0f,  256, As, Bs); break;
        case 3: gemm_tile(pos, Wqkv,           bqkv,     nullptr, qr,     D2,   0.25f, 128, As, Bs); break;
        case 4: gemm_tile(pos, Wqkv + 128*128, bqkv+128, nullptr, kr,     D2,   1.0f,  128, As, Bs); break;
    }
}

// ---------------- scores v4: v2 tile (64i x 128v, micro 4x8) + transposed vec4 window ----
// Window tables stored [cc][d] (stride 200, = 0 mod 8) -> 3x LDS.128 per table per cc.
// Ks stride 18 kills the half-warp 2-way conflict. cc-rotation keeps Qs conflict-free.
template<int SGN>
__global__ __launch_bounds__(256, 3)
void k_scores(const float* __restrict__ q, const float* __restrict__ kv,
              const float* __restrict__ qr, const float* __restrict__ kr,
              float* __restrict__ attn) {
    __shared__ __align__(16) float Qs[64*17];
    __shared__ __align__(16) float Ks[128*18];
    __shared__ __align__(16) float QRt[16*200];   // [cc][d], 192 d-rows used
    __shared__ __align__(16) float KRt[16*200];
    int i0 = (blockIdx.x >> 1) * 64;
    int v0 = (blockIdx.x & 1) * 128;
    int e = blockIdx.y, n = blockIdx.z;
    int tid = threadIdx.x;
    int dmin = (SGN > 0) ? (128 + i0 - v0) : (192 - i0 + v0);
    for (int idx = tid; idx < 64*16; idx += 256) {
        int r = idx >> 4, cc = idx & 15;
        Qs[r*17+cc] = q[(size_t)((i0+r)*NB + n)*C + e*16 + cc];
    }
    for (int idx = tid; idx < 128*16; idx += 256) {
        int r = idx >> 4, cc = idx & 15;
        Ks[r*18+cc] = kv[(size_t)((v0+r)*NB + n)*(2*C) + e*16 + cc];
    }
    for (int idx = tid; idx < 192*16; idx += 256) {
        int r = idx >> 4, cc = idx & 15;
        QRt[cc*200 + r] = qr[(dmin+r)*C + e*16 + cc];
        KRt[cc*200 + r] = kr[(dmin+r)*C + e*16 + cc];
    }
    __syncthreads();
    int ty = tid & 15, tx = tid >> 4;
    int ib = ty*4, vb = tx*8;
    int ccr = ty;
    int dbase = (SGN > 0) ? (127 + ib - vb) : (63 - ib + vb);
    int A = (SGN > 0) ? (dbase - 7) : (dbase - 3);   // ascending 11-value span, A = 0 mod 4
    float acc[4][8] = {};
    #pragma unroll 2
    for (int cs = 0; cs < 16; cs++) {
        int cc = (cs + ccr) & 15;
        float qa[4], ka[8];
        #pragma unroll
        for (int r = 0; r < 4; r++) qa[r] = Qs[(ib+r)*17 + cc];
        #pragma unroll
        for (int r = 0; r < 8; r++) ka[r] = Ks[(vb+r)*18 + cc];
        const float4* qp = (const float4*)&QRt[cc*200 + A];
        const float4* kp = (const float4*)&KRt[cc*200 + A];
        float4 q0 = qp[0], q1 = qp[1], q2 = qp[2];
        float4 k0 = kp[0], k1 = kp[1], k2 = kp[2];
        float qrw[12] = {q0.x,q0.y,q0.z,q0.w, q1.x,q1.y,q1.z,q1.w, q2.x,q2.y,q2.z,q2.w};
        float krw[12] = {k0.x,k0.y,k0.z,k0.w, k1.x,k1.y,k1.z,k1.w, k2.x,k2.y,k2.z,k2.w};
        #pragma unroll
        for (int ri = 0; ri < 4; ri++)
            #pragma unroll
            for (int rv = 0; rv < 8; rv++) {
                int k = ri - rv + 7;                 // 0..10
                int wi = (SGN > 0) ? k : (10 - k);   // window index (compile-time)
                acc[ri][rv] += qa[ri]*(ka[rv] + krw[wi]) + qrw[wi]*ka[rv];
            }
    }
    #pragma unroll
    for (int ri = 0; ri < 4; ri++) {
        int i = i0 + ib + ri;
        float4* dst = (float4*)&attn[ ((size_t)(n*NE + e)*W + i)*W + v0 + vb ];
        dst[0] = make_float4(acc[ri][0], acc[ri][1], acc[ri][2], acc[ri][3]);
        dst[1] = make_float4(acc[ri][4], acc[ri][5], acc[ri][6], acc[ri][7]);
    }
}

// ---------------- rawsum: rawout[(b,h),i,v] = sum_e attn[n,e,i,v] (memory-bound) --------
__global__ void k_rawsum(const float* __restrict__ attn, float* __restrict__ rawout) {
    int i = blockIdx.x, n = blockIdx.y;
    int v = threadIdx.x;   // 256
    const float* base = attn + ((size_t)(n*NE)*W + i)*W + v;
    float s = 0.f;
    #pragma unroll
    for (int e = 0; e < NE; e++) s += base[(size_t)e*W*W];
    int b = n & 1, h = n >> 1;
    rawout[ ((size_t)(b*HN + h)*W + i)*W + v ] = s;
}

// ---------------- fused online-softmax + AV; v-chunk 16, single-wave occupancy ----------
__global__ __launch_bounds__(128, 8)
void k_av(const float* __restrict__ attn, const float* __restrict__ kv,
          float* __restrict__ vo) {
    __shared__ float Ps[256*17];                 // stride 17: conflict-free scalar reads
    __shared__ __align__(16) float Vs[16*20];    // stride 20: aligned float4 broadcast reads
    int e = blockIdx.x, n = blockIdx.y;
    int t = threadIdx.x;     // 128: rows t and t+128
    float acc[2][16] = {};
    float m0 = -1e30f, m1 = -1e30f, s0 = 0.f, s1 = 0.f;
    const float* P = attn + (size_t)(n*NE + e)*W*W;
    for (int v0 = 0; v0 < W; v0 += 16) {
        __syncthreads();
        #pragma unroll
        for (int k = 0; k < 32; k++) {
            int idx = t + k*128;
            int ii = idx >> 4, vv = idx & 15;
            Ps[ii*17 + vv] = P[(size_t)ii*W + v0 + vv];
        }
        if (t < 64) {
            int vv = t >> 2, cc4 = t & 3;
            float4 vx = *(const float4*)&kv[(size_t)((v0+vv)*NB + n)*(2*C) + C + e*16 + cc4*4];
            *(float4*)&Vs[vv*20 + cc4*4] = vx;
        }
        __syncthreads();
        float cm0 = -1e30f, cm1 = -1e30f;
        #pragma unroll
        for (int vv = 0; vv < 16; vv++) {
            cm0 = fmaxf(cm0, Ps[t*17 + vv]);
            cm1 = fmaxf(cm1, Ps[(t+128)*17 + vv]);
        }
        if (cm0 > m0) {
            float c = __expf(m0 - cm0);
            s0 *= c;
            #pragma unroll
            for (int cc = 0; cc < 16; cc++) acc[0][cc] *= c;
            m0 = cm0;
        }
        if (cm1 > m1) {
            float c = __expf(m1 - cm1);
            s1 *= c;
            #pragma unroll
            for (int cc = 0; cc < 16; cc++) acc[1][cc] *= c;
            m1 = cm1;
        }
        #pragma unroll 4
        for (int vv = 0; vv < 16; vv++) {
            float p0 = __expf(Ps[t*17 + vv] - m0);
            float p1 = __expf(Ps[(t+128)*17 + vv] - m1);
            s0 += p0; s1 += p1;
            #pragma unroll
            for (int c4 = 0; c4 < 4; c4++) {
                float4 vx = *(const float4*)&Vs[vv*20 + c4*4];
                acc[0][c4*4+0] += p0*vx.x; acc[0][c4*4+1] += p0*vx.y;
                acc[0][c4*4+2] += p0*vx.z; acc[0][c4*4+3] += p0*vx.w;
                acc[1][c4*4+0] += p1*vx.x; acc[1][c4*4+1] += p1*vx.y;
                acc[1][c4*4+2] += p1*vx.z; acc[1][c4*4+3] += p1*vx.w;
            }
        }
    }
    float inv0 = 1.0f/s0, inv1 = 1.0f/s1;
    {
        float4* dst = (float4*)&vo[(size_t)((size_t)t*NB + n)*C + e*16];
        dst[0] = make_float4(acc[0][0]*inv0, acc[0][1]*inv0, acc[0][2]*inv0, acc[0][3]*inv0);
        dst[1] = make_float4(acc[0][4]*inv0, acc[0][5]*inv0, acc[0][6]*inv0, acc[0][7]*inv0);
        dst[2] = make_float4(acc[0][8]*inv0, acc[0][9]*inv0, acc[0][10]*inv0, acc[0][11]*inv0);
        dst[3] = make_float4(acc[0][12]*inv0, acc[0][13]*inv0, acc[0][14]*inv0, acc[0][15]*inv0);
    }
    {
        float4* dst = (float4*)&vo[(size_t)((size_t)(t+128)*NB + n)*C + e*16];
        dst[0] = make_float4(acc[1][0]*inv1, acc[1][1]*inv1, acc[1][2]*inv1, acc[1][3]*inv1);
        dst[1] = make_float4(acc[1][4]*inv1, acc[1][5]*inv1, acc[1][6]*inv1, acc[1][7]*inv1);
        dst[2] = make_float4(acc[1][8]*inv1, acc[1][9]*inv1, acc[1][10]*inv1, acc[1][11]*inv1);
        dst[3] = make_float4(acc[1][12]*inv1, acc[1][13]*inv1, acc[1][14]*inv1, acc[1][15]*inv1);
    }
}

// ---------------- host ----------------
extern "C" void kernel_launch(void* const* d_in, const int* in_sizes, int n_in,
                              void* d_out, int out_size) {
    const float* feat_left  = (const float*)d_in[0];
    const float* feat_right = (const float*)d_in[1];
    const float* pos        = (const float*)d_in[2];
    // d_in[3] pos_indexes: analytic d = 255 +/- (i-v) used instead
    const float* Wqkv = (const float*)d_in[4];
    const float* bqkv = (const float*)d_in[5];
    const float* Wo   = (const float*)d_in[6];
    const float* bo   = (const float*)d_in[7];
    const float* g1   = (const float*)d_in[8];
    const float* b1   = (const float*)d_in[9];
    const float* g2   = (const float*)d_in[10];
    const float* b2   = (const float*)d_in[11];
    float* out = (float*)d_out;

    float *fl,*fr,*fl2,*fr2,*q,*kv,*qr,*kr,*attn;
    cudaGetSymbolAddress((void**)&fl,   g_fl);
    cudaGetSymbolAddress((void**)&fr,   g_fr);
    cudaGetSymbolAddress((void**)&fl2,  g_fl2);
    cudaGetSymbolAddress((void**)&fr2,  g_fr2);
    cudaGetSymbolAddress((void**)&q,    g_q);
    cudaGetSymbolAddress((void**)&kv,   g_kv);
    cudaGetSymbolAddress((void**)&qr,   g_qr);
    cudaGetSymbolAddress((void**)&kr,   g_kr);
    cudaGetSymbolAddress((void**)&attn, g_attn);
    float* vo = q;   // q dead after k_scores/k_rawsum; k_av may overwrite

    dim3 bt(32, 8);
    dim3 gt2(8, 4, 256);   // z = hb(128) * src(2)

    // to_seq (both) + LN(g1,b1) (both)
    k_reorder_in<<<gt2, bt>>>(feat_right, fr, feat_left, fl);
    k_layernorm2<<<dim3(ROWS,2), 128>>>(fr, fr2, fl, fl2, g1, b1);

    // all projections for MHA1 + positional tables, one z-batched launch
    k_gemm_qkv<<<dim3(512,1,5), 256>>>(fr2, fl2, pos, Wqkv, bqkv, q, kv, qr, kr);

    // MHA1: d = 255 - (i - v)
    k_scores<-1><<<dim3(8, NE, NB), 256>>>(q, kv, qr, kr, attn);
    k_av<<<dim3(NE, NB), 128>>>(attn, kv, vo);
    k_gemm<<<dim3(512,1), 256>>>(vo, Wo, bo, fr, fr, ROWS, 1.0f, 128);  // fr += upd_r

    // fr2 <- ln(fr, g2, b2)
    k_layernorm2<<<dim3(ROWS,1), 128>>>(fr, fr2, nullptr, nullptr, g2, b2);

    // MHA2: d = 255 + (i - v)
    k_gemm_qkv<<<dim3(512,1,3), 256>>>(fl2, fr2, pos, Wqkv, bqkv, q, kv, qr, kr);
    k_scores<1><<<dim3(8, NE, NB), 256>>>(q, kv, qr, kr, attn);
    k_rawsum<<<dim3(W, NB), 256>>>(attn, out + 8388608);
    k_av<<<dim3(NE, NB), 128>>>(attn, kv, vo);
    k_gemm<<<dim3(512,1), 256>>>(vo, Wo, bo, fl, fl, ROWS, 1.0f, 128);  // fl += upd_l

    // from_seq (both)
    k_reorder_out<<<gt2, bt>>>(fl, out, fr, out + 4194304);
}